// round 3
// baseline (speedup 1.0000x reference)
#include <cuda_runtime.h>
#include <math.h>

#define PP 64
#define BB 2048
#define HH 128
#define NIN 2

constexpr int MT   = 128;   // rows per CTA
constexpr int LDS_ = 132;   // padded smem row stride (floats) -> conflict-free frags
constexpr long ENC_SZ = (long)BB * PP * HH;       // 16777216
constexpr long HN_SZ  = (long)PP * 2 * BB * HH;   // 33554432

__device__ __forceinline__ unsigned f2tf(float x) {
    unsigned u;
    asm("cvt.rna.tf32.f32 %0, %1;" : "=r"(u) : "f"(x));
    return u;
}
__device__ __forceinline__ float sigf(float x) {
    return 1.0f / (1.0f + expf(-x));
}

// One LSTM layer, fully fused: gates GEMM (TF32 tensor cores) + cell update.
// Gate columns are permuted: np = unit*4 + gate within a 128-col n-block, so a
// CTA's 128 columns = 32 complete units -> elementwise fuses with no scratch.
template <int LAYER>
__global__ __launch_bounds__(256) void lstm_layer(
    const float* __restrict__ xin,
    const float* __restrict__ h0,
    const float* __restrict__ c0,
    const float* __restrict__ Wih0,
    const float* __restrict__ Whh0,
    const float* __restrict__ bih0,
    const float* __restrict__ bhh0,
    const float* __restrict__ Wih1,
    const float* __restrict__ Whh1,
    const float* __restrict__ bih1,
    const float* __restrict__ bhh1,
    float* __restrict__ dout)
{
    extern __shared__ float smem[];
    float* sA = smem;                // [128][132] activation tile (TF32 bits)
    float* sW = smem + MT * LDS_;    // [128][132] permuted weight tile
    float* sG = sA;                  // epilogue gate buffer (reuses sA)

    const int tid   = threadIdx.x;
    const int lane  = tid & 31;
    const int wid   = tid >> 5;
    const int grp   = lane >> 2;     // 0..7
    const int t4    = lane & 3;      // 0..3
    const int warpM = wid & 3;       // 4 warps along M
    const int warpN = wid >> 2;      // 2 warps along N

    const int nb = blockIdx.x;       // 0..3   (n-block: units [nb*32, nb*32+32))
    const int mb = blockIdx.y;       // 0..1023
    const int p  = mb >> 4;          // 16 row-blocks per pedestrian (B/MT = 16)
    const int b0 = (mb & 15) * MT;

    float acc[2][8][4];
    #pragma unroll
    for (int i = 0; i < 2; i++)
        #pragma unroll
        for (int j = 0; j < 8; j++)
            #pragma unroll
            for (int k = 0; k < 4; k++) acc[i][j][k] = 0.f;

    const int NSRC = (LAYER == 0) ? 1 : 2;
    for (int s = 0; s < NSRC; s++) {
        const float* Abase;
        const float* Wsel;
        if (LAYER == 0) {
            Abase = h0 + ((long)(p * 2 + 0) * BB + b0) * HH;   // h0 layer-0 state
            Wsel  = Whh0;
        } else if (s == 0) {
            Abase = dout + ENC_SZ + ((long)(p * 2 + 0) * BB + b0) * HH;  // h1 from layer-0
            Wsel  = Wih1;
        } else {
            Abase = h0 + ((long)(p * 2 + 1) * BB + b0) * HH;   // h0 layer-1 state
            Wsel  = Whh1;
        }

        // ---- load A tile (128 x 128), convert to TF32 on store ----
        #pragma unroll
        for (int it = 0; it < 16; it++) {
            int idx = it * 256 + tid;
            int row = idx >> 5, q = idx & 31;
            const float4 v = *(const float4*)(Abase + (long)row * HH + q * 4);
            float* d = sA + row * LDS_ + q * 4;
            d[0] = __uint_as_float(f2tf(v.x));
            d[1] = __uint_as_float(f2tf(v.y));
            d[2] = __uint_as_float(f2tf(v.z));
            d[3] = __uint_as_float(f2tf(v.w));
        }
        // ---- load permuted W tile: np -> orig row (np&3)*128 + nb*32 + (np>>2) ----
        #pragma unroll
        for (int it = 0; it < 16; it++) {
            int idx = it * 256 + tid;
            int np = idx >> 5, q = idx & 31;
            int norig = (np & 3) * HH + nb * 32 + (np >> 2);
            const float4 v = *(const float4*)(Wsel + (long)norig * HH + q * 4);
            float* d = sW + np * LDS_ + q * 4;
            d[0] = __uint_as_float(f2tf(v.x));
            d[1] = __uint_as_float(f2tf(v.y));
            d[2] = __uint_as_float(f2tf(v.z));
            d[3] = __uint_as_float(f2tf(v.w));
        }
        __syncthreads();

        // ---- mainloop: 16 k-steps of m16n8k8 TF32 mma ----
        #pragma unroll
        for (int k0 = 0; k0 < 16; k0++) {
            const int kk = k0 * 8;
            unsigned a[2][4];
            #pragma unroll
            for (int mt = 0; mt < 2; mt++) {
                int r = warpM * 32 + mt * 16 + grp;
                const float* base = sA + r * LDS_ + kk + t4;
                a[mt][0] = __float_as_uint(base[0]);
                a[mt][1] = __float_as_uint(base[8 * LDS_]);
                a[mt][2] = __float_as_uint(base[4]);
                a[mt][3] = __float_as_uint(base[8 * LDS_ + 4]);
            }
            #pragma unroll
            for (int nt = 0; nt < 8; nt++) {
                int col = warpN * 64 + nt * 8 + grp;
                const float* wb = sW + col * LDS_ + kk + t4;
                unsigned br0 = __float_as_uint(wb[0]);
                unsigned br1 = __float_as_uint(wb[4]);
                #pragma unroll
                for (int mt = 0; mt < 2; mt++) {
                    asm volatile(
                        "mma.sync.aligned.m16n8k8.row.col.f32.tf32.tf32.f32 "
                        "{%0,%1,%2,%3}, {%4,%5,%6,%7}, {%8,%9}, {%0,%1,%2,%3};\n"
                        : "+f"(acc[mt][nt][0]), "+f"(acc[mt][nt][1]),
                          "+f"(acc[mt][nt][2]), "+f"(acc[mt][nt][3])
                        : "r"(a[mt][0]), "r"(a[mt][1]), "r"(a[mt][2]), "r"(a[mt][3]),
                          "r"(br0), "r"(br1));
                }
            }
        }
        __syncthreads();
    }

    // ---- accumulators -> smem gate buffer ----
    #pragma unroll
    for (int mt = 0; mt < 2; mt++) {
        #pragma unroll
        for (int nt = 0; nt < 8; nt++) {
            int r   = warpM * 32 + mt * 16 + grp;
            int col = warpN * 64 + nt * 8 + t4 * 2;
            sG[r * LDS_ + col]           = acc[mt][nt][0];
            sG[r * LDS_ + col + 1]       = acc[mt][nt][1];
            sG[(r + 8) * LDS_ + col]     = acc[mt][nt][2];
            sG[(r + 8) * LDS_ + col + 1] = acc[mt][nt][3];
        }
    }
    __syncthreads();

    // ---- fused LSTM cell epilogue ----
    const float* bi = (LAYER == 0) ? bih0 : bih1;
    const float* bh = (LAYER == 0) ? bhh0 : bhh1;
    float* out_enc = dout;
    float* out_h   = dout + ENC_SZ;
    float* out_c   = dout + ENC_SZ + HN_SZ;

    #pragma unroll
    for (int it = 0; it < 16; it++) {
        int cell = it * 256 + tid;        // 4096 unit-cells: 128 rows x 32 units
        int ml = cell >> 5, jl = cell & 31;
        int b = b0 + ml;
        int j = nb * 32 + jl;

        const float4 g4 = *(const float4*)(sG + ml * LDS_ + jl * 4);
        float gi = g4.x + bi[j]          + bh[j];
        float gf = g4.y + bi[HH + j]     + bh[HH + j];
        float gg = g4.z + bi[2 * HH + j] + bh[2 * HH + j];
        float go = g4.w + bi[3 * HH + j] + bh[3 * HH + j];

        if (LAYER == 0) {
            const float x0 = xin[((long)b * PP + p) * NIN + 0];
            const float x1 = xin[((long)b * PP + p) * NIN + 1];
            gi += x0 * Wih0[(0 * HH + j) * NIN + 0] + x1 * Wih0[(0 * HH + j) * NIN + 1];
            gf += x0 * Wih0[(1 * HH + j) * NIN + 0] + x1 * Wih0[(1 * HH + j) * NIN + 1];
            gg += x0 * Wih0[(2 * HH + j) * NIN + 0] + x1 * Wih0[(2 * HH + j) * NIN + 1];
            go += x0 * Wih0[(3 * HH + j) * NIN + 0] + x1 * Wih0[(3 * HH + j) * NIN + 1];
        }

        const long sidx = ((long)(p * 2 + LAYER) * BB + b) * HH + j;
        const float cprev = c0[sidx];
        const float cn = sigf(gf) * cprev + sigf(gi) * tanhf(gg);
        const float hn = sigf(go) * tanhf(cn);

        out_h[sidx] = hn;
        out_c[sidx] = cn;
        if (LAYER == 1) out_enc[((long)b * PP + p) * HH + j] = hn;
    }
}

extern "C" void kernel_launch(void* const* d_in, const int* in_sizes, int n_in,
                              void* d_out, int out_size)
{
    const float* xin  = (const float*)d_in[0];
    const float* h0   = (const float*)d_in[1];
    const float* c0   = (const float*)d_in[2];
    const float* Wih0 = (const float*)d_in[3];
    const float* Whh0 = (const float*)d_in[4];
    const float* bih0 = (const float*)d_in[5];
    const float* bhh0 = (const float*)d_in[6];
    const float* Wih1 = (const float*)d_in[7];
    const float* Whh1 = (const float*)d_in[8];
    const float* bih1 = (const float*)d_in[9];
    const float* bhh1 = (const float*)d_in[10];
    float* dout = (float*)d_out;

    const int smem_bytes = 2 * MT * LDS_ * (int)sizeof(float);  // 135168

    cudaFuncSetAttribute(lstm_layer<0>, cudaFuncAttributeMaxDynamicSharedMemorySize, smem_bytes);
    cudaFuncSetAttribute(lstm_layer<1>, cudaFuncAttributeMaxDynamicSharedMemorySize, smem_bytes);

    dim3 grid(4, 1024);  // 4 n-blocks x 1024 m-blocks
    lstm_layer<0><<<grid, 256, smem_bytes>>>(xin, h0, c0, Wih0, Whh0, bih0, bhh0,
                                             Wih1, Whh1, bih1, bhh1, dout);
    lstm_layer<1><<<grid, 256, smem_bytes>>>(xin, h0, c0, Wih0, Whh0, bih0, bhh0,
                                             Wih1, Whh1, bih1, bhh1, dout);
}

// round 4
// speedup vs baseline: 1.5142x; 1.5142x over previous
#include <cuda_runtime.h>
#include <math.h>

#define PP 64
#define BB 2048
#define HH 128
#define NIN 2

constexpr int MT   = 64;    // rows per CTA (halved -> 2 CTAs/SM)
constexpr int LDS_ = 132;   // padded smem row stride (floats) -> conflict-free ldmatrix
constexpr long ENC_SZ = (long)BB * PP * HH;       // 16777216
constexpr long HN_SZ  = (long)PP * 2 * BB * HH;   // 33554432

__device__ __forceinline__ float sigf(float x) { return 1.0f / (1.0f + expf(-x)); }

__device__ __forceinline__ unsigned sptr(const void* p) {
    return (unsigned)__cvta_generic_to_shared(p);
}
__device__ __forceinline__ void cp16(void* s, const void* g) {
    asm volatile("cp.async.cg.shared.global [%0], [%1], 16;\n" :: "r"(sptr(s)), "l"(g));
}
__device__ __forceinline__ void cp_wait_all() {
    asm volatile("cp.async.commit_group;\ncp.async.wait_group 0;\n" ::: "memory");
}
__device__ __forceinline__ void ldsm4(unsigned& r0, unsigned& r1, unsigned& r2, unsigned& r3,
                                      const void* p) {
    asm volatile("ldmatrix.sync.aligned.m8n8.x4.shared.b16 {%0,%1,%2,%3}, [%4];\n"
                 : "=r"(r0), "=r"(r1), "=r"(r2), "=r"(r3)
                 : "r"(sptr(p)));
}

// One LSTM layer: gates GEMM (TF32 mma, raw-f32-as-tf32 truncation) + fused cell.
// Gate columns permuted (np = unit*4 + gate) so each CTA owns complete units.
template <int LAYER>
__global__ __launch_bounds__(256, 2) void lstm_layer(
    const float* __restrict__ xin,
    const float* __restrict__ h0,
    const float* __restrict__ c0,
    const float* __restrict__ Wih0,
    const float* __restrict__ Whh0,
    const float* __restrict__ bih0,
    const float* __restrict__ bhh0,
    const float* __restrict__ Wih1,
    const float* __restrict__ Whh1,
    const float* __restrict__ bih1,
    const float* __restrict__ bhh1,
    float* __restrict__ dout)
{
    extern __shared__ float smem[];
    float* sA = smem;                // [64][132]  activation tile
    float* sW = smem + MT * LDS_;    // [128][132] permuted weight tile
    float* sG = sA;                  // epilogue gate buffer (reuses sA)

    const int tid  = threadIdx.x;
    const int lane = tid & 31;
    const int wid  = tid >> 5;
    const int grp  = lane >> 2;      // 0..7
    const int t4   = lane & 3;       // 0..3
    const int warpM = wid & 1;       // 2 warps along M (32 rows each)
    const int warpN = wid >> 1;      // 4 warps along N (32 cols each)

    const int nb = blockIdx.x;       // 0..3 : units [nb*32, nb*32+32)
    const int mb = blockIdx.y;       // 0..2047 ; 32 row-blocks per pedestrian
    const int p  = mb >> 5;
    const int b0 = (mb & 31) * MT;

    float acc[2][4][4];
    #pragma unroll
    for (int i = 0; i < 2; i++)
        #pragma unroll
        for (int j = 0; j < 4; j++)
            #pragma unroll
            for (int k = 0; k < 4; k++) acc[i][j][k] = 0.f;

    const int NSRC = (LAYER == 0) ? 1 : 2;
    for (int s = 0; s < NSRC; s++) {
        const float* Abase;
        const float* Wsel;
        if (LAYER == 0) {
            Abase = h0 + ((long)(p * 2 + 0) * BB + b0) * HH;                 // h0 L0 state
            Wsel  = Whh0;
        } else if (s == 0) {
            Abase = dout + ENC_SZ + ((long)(p * 2 + 0) * BB + b0) * HH;      // h1 from L0
            Wsel  = Wih1;
        } else {
            Abase = h0 + ((long)(p * 2 + 1) * BB + b0) * HH;                 // h0 L1 state
            Wsel  = Whh1;
        }

        // ---- async fill A tile (64 x 128) ----
        #pragma unroll
        for (int it = 0; it < 8; it++) {
            int idx = it * 256 + tid;           // 2048 16B chunks
            int row = idx >> 5, q = idx & 31;
            cp16(sA + row * LDS_ + q * 4, Abase + (long)row * HH + q * 4);
        }
        // ---- async fill permuted W tile: np -> orig row (np&3)*128 + nb*32 + (np>>2) ----
        #pragma unroll
        for (int it = 0; it < 16; it++) {
            int idx = it * 256 + tid;           // 4096 16B chunks
            int np = idx >> 5, q = idx & 31;
            int norig = (np & 3) * HH + nb * 32 + (np >> 2);
            cp16(sW + np * LDS_ + q * 4, Wsel + (long)norig * HH + q * 4);
        }
        cp_wait_all();
        __syncthreads();

        // ---- mainloop: 16 k-steps, ldmatrix.x4 fragments ----
        #pragma unroll
        for (int k0 = 0; k0 < 16; k0++) {
            const int kk = k0 * 8;
            unsigned a[2][4];
            #pragma unroll
            for (int mt = 0; mt < 2; mt++) {
                const int R = warpM * 32 + mt * 16;
                const float* pa = sA + (R + (lane & 15)) * LDS_ + kk + ((lane >> 4) << 2);
                ldsm4(a[mt][0], a[mt][1], a[mt][2], a[mt][3], pa);
            }
            unsigned b[2][4];
            #pragma unroll
            for (int nt2 = 0; nt2 < 2; nt2++) {
                const int C = warpN * 32 + nt2 * 16;
                const float* pb = sW + (C + (lane & 7) + ((lane >> 4) << 3)) * LDS_
                                     + kk + (((lane >> 3) & 1) << 2);
                ldsm4(b[nt2][0], b[nt2][1], b[nt2][2], b[nt2][3], pb);
            }
            #pragma unroll
            for (int mt = 0; mt < 2; mt++) {
                #pragma unroll
                for (int nt = 0; nt < 4; nt++) {
                    const unsigned br0 = b[nt >> 1][(nt & 1) * 2];
                    const unsigned br1 = b[nt >> 1][(nt & 1) * 2 + 1];
                    asm volatile(
                        "mma.sync.aligned.m16n8k8.row.col.f32.tf32.tf32.f32 "
                        "{%0,%1,%2,%3}, {%4,%5,%6,%7}, {%8,%9}, {%0,%1,%2,%3};\n"
                        : "+f"(acc[mt][nt][0]), "+f"(acc[mt][nt][1]),
                          "+f"(acc[mt][nt][2]), "+f"(acc[mt][nt][3])
                        : "r"(a[mt][0]), "r"(a[mt][1]), "r"(a[mt][2]), "r"(a[mt][3]),
                          "r"(br0), "r"(br1));
                }
            }
        }
        __syncthreads();
    }

    // ---- accumulators -> smem gate buffer ----
    #pragma unroll
    for (int mt = 0; mt < 2; mt++) {
        #pragma unroll
        for (int nt = 0; nt < 4; nt++) {
            int r   = warpM * 32 + mt * 16 + grp;
            int col = warpN * 32 + nt * 8 + t4 * 2;
            sG[r * LDS_ + col]           = acc[mt][nt][0];
            sG[r * LDS_ + col + 1]       = acc[mt][nt][1];
            sG[(r + 8) * LDS_ + col]     = acc[mt][nt][2];
            sG[(r + 8) * LDS_ + col + 1] = acc[mt][nt][3];
        }
    }
    __syncthreads();

    // ---- fused LSTM cell epilogue ----
    const float* bi = (LAYER == 0) ? bih0 : bih1;
    const float* bh = (LAYER == 0) ? bhh0 : bhh1;
    float* out_enc = dout;
    float* out_h   = dout + ENC_SZ;
    float* out_c   = dout + ENC_SZ + HN_SZ;

    #pragma unroll
    for (int it = 0; it < 8; it++) {
        int cell = it * 256 + tid;        // 2048 unit-cells: 64 rows x 32 units
        int ml = cell >> 5, jl = cell & 31;
        int b = b0 + ml;
        int j = nb * 32 + jl;

        const float4 g4 = *(const float4*)(sG + ml * LDS_ + jl * 4);
        float gi = g4.x + bi[j]          + bh[j];
        float gf = g4.y + bi[HH + j]     + bh[HH + j];
        float gg = g4.z + bi[2 * HH + j] + bh[2 * HH + j];
        float go = g4.w + bi[3 * HH + j] + bh[3 * HH + j];

        if (LAYER == 0) {
            const float2 x2 = *(const float2*)(xin + ((long)b * PP + p) * NIN);
            const float2 wi = *(const float2*)(Wih0 + (0 * HH + j) * NIN);
            const float2 wf = *(const float2*)(Wih0 + (1 * HH + j) * NIN);
            const float2 wg = *(const float2*)(Wih0 + (2 * HH + j) * NIN);
            const float2 wo = *(const float2*)(Wih0 + (3 * HH + j) * NIN);
            gi += x2.x * wi.x + x2.y * wi.y;
            gf += x2.x * wf.x + x2.y * wf.y;
            gg += x2.x * wg.x + x2.y * wg.y;
            go += x2.x * wo.x + x2.y * wo.y;
        }

        const long sidx = ((long)(p * 2 + LAYER) * BB + b) * HH + j;
        const float cprev = c0[sidx];
        const float cn = sigf(gf) * cprev + sigf(gi) * tanhf(gg);
        const float hn = sigf(go) * tanhf(cn);

        out_h[sidx] = hn;
        out_c[sidx] = cn;
        if (LAYER == 1) out_enc[((long)b * PP + p) * HH + j] = hn;
    }
}

extern "C" void kernel_launch(void* const* d_in, const int* in_sizes, int n_in,
                              void* d_out, int out_size)
{
    const float* xin  = (const float*)d_in[0];
    const float* h0   = (const float*)d_in[1];
    const float* c0   = (const float*)d_in[2];
    const float* Wih0 = (const float*)d_in[3];
    const float* Whh0 = (const float*)d_in[4];
    const float* bih0 = (const float*)d_in[5];
    const float* bhh0 = (const float*)d_in[6];
    const float* Wih1 = (const float*)d_in[7];
    const float* Whh1 = (const float*)d_in[8];
    const float* bih1 = (const float*)d_in[9];
    const float* bhh1 = (const float*)d_in[10];
    float* dout = (float*)d_out;

    const int smem_bytes = (MT + 128) * LDS_ * (int)sizeof(float);  // 101376

    cudaFuncSetAttribute(lstm_layer<0>, cudaFuncAttributeMaxDynamicSharedMemorySize, smem_bytes);
    cudaFuncSetAttribute(lstm_layer<1>, cudaFuncAttributeMaxDynamicSharedMemorySize, smem_bytes);

    dim3 grid(4, 2048);  // 4 n-blocks x 2048 m-blocks
    lstm_layer<0><<<grid, 256, smem_bytes>>>(xin, h0, c0, Wih0, Whh0, bih0, bhh0,
                                             Wih1, Whh1, bih1, bhh1, dout);
    lstm_layer<1><<<grid, 256, smem_bytes>>>(xin, h0, c0, Wih0, Whh0, bih0, bhh0,
                                             Wih1, Whh1, bih1, bhh1, dout);
}